// round 2
// baseline (speedup 1.0000x reference)
#include <cuda_runtime.h>
#include <cuda_bf16.h>

#define NN       256
#define NWARPS   8
#define NTHREADS 256
#define NITER    15
#define RB       8      // rows batched per warp inner loop (MLP depth)

static __device__ __forceinline__ float rcp_nn(float u) {
    // divide_no_nan semantics: 0 where denominator is 0
    return (u == 0.0f) ? 0.0f : __frcp_rn(u);
}

__global__ void __launch_bounds__(NTHREADS, 1)
sinkhorn_kernel(const float* __restrict__ g_in, float* __restrict__ g_out)
{
    __shared__ float s_ru[NN];            // reciprocal column sums (current iter)
    __shared__ float s_part[NWARPS][NN];  // per-warp partial column sums

    const int tid  = threadIdx.x;
    const int wid  = tid >> 5;
    const int lane = tid & 31;
    const int c0   = 4 * lane;            // my cols c0..c0+3
    const int c1   = 128 + 4 * lane;      // my cols c1..c1+3
    const int row0 = wid * 32;            // my warp's row block

    const float* __restrict__ src = g_in  + (size_t)blockIdx.x * NN * NN;
    float*       __restrict__ dst = g_out + (size_t)blockIdx.x * NN * NN;

    // ---- pre-pass: column sums of the input -> s_ru ----
    {
        float4 cs0 = make_float4(0.f, 0.f, 0.f, 0.f);
        float4 cs1 = make_float4(0.f, 0.f, 0.f, 0.f);
        for (int rb = 0; rb < 32; rb += RB) {
            float4 a0[RB], a1[RB];
            #pragma unroll
            for (int r = 0; r < RB; ++r) {
                const float* rp = src + (row0 + rb + r) * NN;
                a0[r] = *(const float4*)(rp + c0);
                a1[r] = *(const float4*)(rp + c1);
            }
            #pragma unroll
            for (int r = 0; r < RB; ++r) {
                cs0.x += a0[r].x; cs0.y += a0[r].y; cs0.z += a0[r].z; cs0.w += a0[r].w;
                cs1.x += a1[r].x; cs1.y += a1[r].y; cs1.z += a1[r].z; cs1.w += a1[r].w;
            }
        }
        *(float4*)&s_part[wid][c0] = cs0;
        *(float4*)&s_part[wid][c1] = cs1;
        __syncthreads();
        float u = 0.f;
        #pragma unroll
        for (int w = 0; w < NWARPS; ++w) u += s_part[w][tid];
        s_ru[tid] = rcp_nn(u);
        __syncthreads();
    }

    const float* rd = src;   // iteration 0 reads the input; afterwards in-place on dst
    for (int it = 0; it < NITER; ++it) {
        const float4 ru0 = *(const float4*)&s_ru[c0];
        const float4 ru1 = *(const float4*)&s_ru[c1];
        float4 cs0 = make_float4(0.f, 0.f, 0.f, 0.f);
        float4 cs1 = make_float4(0.f, 0.f, 0.f, 0.f);

        for (int rb = 0; rb < 32; rb += RB) {
            float4 a0[RB], a1[RB];
            #pragma unroll
            for (int r = 0; r < RB; ++r) {
                const float* rp = rd + (row0 + rb + r) * NN;
                a0[r] = *(const float4*)(rp + c0);
                a1[r] = *(const float4*)(rp + c1);
            }
            #pragma unroll
            for (int r = 0; r < RB; ++r) {
                float4 h0, h1;
                h0.x = a0[r].x * ru0.x; h0.y = a0[r].y * ru0.y;
                h0.z = a0[r].z * ru0.z; h0.w = a0[r].w * ru0.w;
                h1.x = a1[r].x * ru1.x; h1.y = a1[r].y * ru1.y;
                h1.z = a1[r].z * ru1.z; h1.w = a1[r].w * ru1.w;

                float s = ((h0.x + h0.y) + (h0.z + h0.w))
                        + ((h1.x + h1.y) + (h1.z + h1.w));
                #pragma unroll
                for (int off = 16; off; off >>= 1)
                    s += __shfl_xor_sync(0xFFFFFFFFu, s, off);

                const float rv = rcp_nn(s);
                h0.x *= rv; h0.y *= rv; h0.z *= rv; h0.w *= rv;
                h1.x *= rv; h1.y *= rv; h1.z *= rv; h1.w *= rv;

                // accumulate next iteration's column sums in registers
                cs0.x += h0.x; cs0.y += h0.y; cs0.z += h0.z; cs0.w += h0.w;
                cs1.x += h1.x; cs1.y += h1.y; cs1.z += h1.z; cs1.w += h1.w;

                float* wp = dst + (row0 + rb + r) * NN;
                *(float4*)(wp + c0) = h0;
                *(float4*)(wp + c1) = h1;
            }
        }

        // cross-warp reduction of column-sum partials -> next recip_u
        *(float4*)&s_part[wid][c0] = cs0;
        *(float4*)&s_part[wid][c1] = cs1;
        __syncthreads();
        {
            float u = 0.f;
            #pragma unroll
            for (int w = 0; w < NWARPS; ++w) u += s_part[w][tid];
            s_ru[tid] = rcp_nn(u);
        }
        __syncthreads();
        rd = dst;
    }
}

extern "C" void kernel_launch(void* const* d_in, const int* in_sizes, int n_in,
                              void* d_out, int out_size) {
    const float* x = (const float*)d_in[0];
    float* y = (float*)d_out;
    const int B = in_sizes[0] / (NN * NN);
    sinkhorn_kernel<<<B, NTHREADS>>>(x, y);
}